// round 6
// baseline (speedup 1.0000x reference)
#include <cuda_runtime.h>
#include <cstdint>
#include <cstddef>

#define XWID  14
#define XPAD  16
#define PROJ  128
#define DM    512
#define LAT   256
#define BB    64
#define SS    512
#define NCW   6
#define INW   768

// ------------- smem layout (float offsets) -------------
#define SM_WHR   0        // [j<64][128]                8192
#define SM_H     8192     // [b<4][128]                 512
#define SM_PB    8704     // [par<2][dout<128][b<4]     1024
#define SM_GATE  9728     // [gt<4][b<4][64]            1024
#define SM_A     10752    // [b<4][64]                  256
#define SM_CTX   11008    // [b<4][256]                 1024
#define SM_BAR   12032    // 1 x u64 barrier            2
#define SM_X     12040    // [b<4][512][16]             32768
#define SM_TOT_FLOATS 44808
#define SM_TOT_BYTES  (SM_TOT_FLOATS * 4)

// history for head kernel
__device__ __align__(16) float g_hs[(size_t)BB * SS * PROJ];

// ---------------- helpers ----------------
static __device__ __forceinline__ uint32_t su32(const void* p) {
    return (uint32_t)__cvta_generic_to_shared(p);
}
static __device__ __forceinline__ uint32_t mapa_rank(uint32_t a, uint32_t r) {
    uint32_t o;
    asm("mapa.shared::cluster.u32 %0, %1, %2;" : "=r"(o) : "r"(a), "r"(r));
    return o;
}
static __device__ __forceinline__ uint32_t ctarank() {
    uint32_t r;
    asm("mov.u32 %0, %%cluster_ctarank;" : "=r"(r));
    return r;
}
static __device__ __forceinline__ void cl_sync() {
    asm volatile("barrier.cluster.arrive.aligned;" ::: "memory");
    asm volatile("barrier.cluster.wait.aligned;" ::: "memory");
}
static __device__ __forceinline__ void mbar_init(uint32_t bar, uint32_t cnt) {
    asm volatile("mbarrier.init.shared.b64 [%0], %1;" :: "r"(bar), "r"(cnt) : "memory");
}
// release-arrive on a (possibly remote) cluster smem barrier
static __device__ __forceinline__ void mbar_arrive_cluster(uint32_t bar) {
    asm volatile("mbarrier.arrive.release.cluster.shared::cluster.b64 _, [%0];"
                 :: "r"(bar) : "memory");
}
static __device__ __forceinline__ void mbar_wait(uint32_t bar, uint32_t ph) {
    uint32_t done;
    asm volatile(
        "{\n\t.reg .pred p;\n\t"
        "mbarrier.try_wait.parity.acquire.cluster.shared::cta.b64 p, [%1], %2;\n\t"
        "selp.b32 %0, 1, 0, p;\n\t}"
        : "=r"(done) : "r"(bar), "r"(ph) : "memory");
    if (!done) {
        asm volatile(
            "{\n\t.reg .pred P1;\n"
            "WL%=:\n\t"
            "mbarrier.try_wait.parity.acquire.cluster.shared::cta.b64 P1, [%0], %1, 0x989680;\n\t"
            "@P1 bra.uni WD%=;\n\t"
            "bra.uni WL%=;\n"
            "WD%=:\n\t}"
            :: "r"(bar), "r"(ph) : "memory");
    }
}
static __device__ __forceinline__ float4 ldsc_v4(uint32_t addr) {
    float4 v;
    asm volatile("ld.shared::cluster.v4.f32 {%0,%1,%2,%3}, [%4];"
                 : "=f"(v.x), "=f"(v.y), "=f"(v.z), "=f"(v.w) : "r"(addr));
    return v;
}
static __device__ __forceinline__ uint64_t pk(float lo, float hi) {
    uint64_t r;
    asm("mov.b64 %0, {%1, %2};" : "=l"(r) : "f"(lo), "f"(hi));
    return r;
}
static __device__ __forceinline__ void upk(uint64_t v, float& lo, float& hi) {
    asm("mov.b64 {%0, %1}, %2;" : "=f"(lo), "=f"(hi) : "l"(v));
}
static __device__ __forceinline__ void fma2(uint64_t& a, uint64_t b, uint64_t c) {
    asm("fma.rn.f32x2 %0, %1, %2, %0;" : "+l"(a) : "l"(b), "l"(c));
}
static __device__ __forceinline__ float ex2f(float x) {
    float r;
    asm("ex2.approx.f32 %0, %1;" : "=f"(r) : "f"(x));
    return r;
}
static __device__ __forceinline__ float rcpf(float x) {
    float r;
    asm("rcp.approx.f32 %0, %1;" : "=f"(r) : "f"(x));
    return r;
}
static __device__ __forceinline__ float fsig(float x) {
    return rcpf(1.0f + ex2f(-1.4426950408889634f * x));
}
static __device__ __forceinline__ float ftanh(float x) {
    return fmaf(-2.0f, rcpf(1.0f + ex2f(2.8853900817779268f * x)), 1.0f);
}
static __device__ __forceinline__ float warp_sum(float v) {
#pragma unroll
    for (int m = 16; m > 0; m >>= 1) v += __shfl_xor_sync(0xffffffffu, v, m);
    return v;
}

// =====================================================================
// Scan kernel: 128 CTAs, cluster 8, 256 threads.
// Cluster handles batches [4*cl, 4*cl+4). Rank owns c-dims [64r,64r+64)
// (gate rows gt*512 + 64r + cl). Per-step h all-reduce is PULL-based:
// each rank writes projection partials locally (parity double buffer),
// release-arrives on every rank's count-8 mbarrier, then every rank
// gathers all 8 partial vectors via ld.shared::cluster and sums.
// One DSMEM round per step, fully symmetric (no owner warps).
// =====================================================================
__global__ void __cluster_dims__(8, 1, 1) __launch_bounds__(256, 1)
scan_kernel(const float* __restrict__ x, const float* __restrict__ ctx,
            const float* __restrict__ cmdW, const float* __restrict__ cmdb,
            const float* __restrict__ coordW, const float* __restrict__ coordb,
            const float* __restrict__ W_ih, const float* __restrict__ W_hh,
            const float* __restrict__ bih, const float* __restrict__ bhh,
            const float* __restrict__ W_hr)
{
    extern __shared__ float sm[];
    float* whr  = sm + SM_WHR;
    float* hbuf = sm + SM_H;
    float* pbuf = sm + SM_PB;
    float* gbuf = sm + SM_GATE;
    float* abuf = sm + SM_A;
    float* ctxs = sm + SM_CTX;
    float* xs   = sm + SM_X;

    const int t = threadIdx.x;
    const uint32_t rank = ctarank();
    const int b4 = (blockIdx.x >> 3) * 4;
    const int gt = t >> 6, cl = t & 63;
    const int row = gt * 512 + (int)rank * 64 + cl;

    // --- W_hh row into packed registers (64 x u64 = 128 floats) ---
    uint64_t w2[64];
    {
        const ulonglong2* p = (const ulonglong2*)(W_hh + (size_t)row * PROJ);
#pragma unroll
        for (int q = 0; q < 32; q++) {
            ulonglong2 v = p[q];
            w2[2 * q] = v.x;
            w2[2 * q + 1] = v.y;
        }
    }

    // ---------------- prologue phase 1: small smem loads ----------------
    float* cw = xs;           // 3072
    float* qw = xs + 3072;    // 4096
    float* bs = xs + 7168;    // 512
    for (int i = t; i < DM * 6; i += 256) cw[i] = cmdW[i];
    for (int i = t; i < DM * 8; i += 256) qw[i] = coordW[i];
    for (int i = t; i < DM; i += 256) bs[i] = cmdb[i] + coordb[i];
    for (int i = t; i < 4 * LAT; i += 256) {
        int b = i >> 8, j = i & 255;
        ctxs[i] = ctx[(size_t)(b4 + b) * LAT + j];
    }
    for (int i = t; i < PROJ * 64; i += 256) {
        int d = i >> 6, j = i & 63;
        whr[j * 128 + d] = W_hr[(size_t)d * DM + rank * 64 + j];
    }
    for (int i = t; i < 512; i += 256) hbuf[i] = 0.0f;
    const uint32_t rdyBar = su32(sm + SM_BAR);
    if (t == 0) mbar_init(rdyBar, 8);
    __syncthreads();

    // ---------------- phase 2: fold input weights + per-batch base -------
    float ac[XWID];
#pragma unroll
    for (int k = 0; k < XWID; k++) ac[k] = 0.0f;
    float gB = bih[row] + bhh[row];
    {
        const float4* wr = (const float4*)(W_ih + (size_t)row * INW);
        for (int d4 = 0; d4 < DM / 4; d4++) {
            float4 w4 = wr[d4];
            float wa[4] = {w4.x, w4.y, w4.z, w4.w};
#pragma unroll
            for (int u = 0; u < 4; u++) {
                int d = d4 * 4 + u;
                float wv = wa[u];
#pragma unroll
                for (int k = 0; k < 6; k++) ac[k] += wv * cw[d * 6 + k];
#pragma unroll
                for (int k = 0; k < 8; k++) ac[6 + k] += wv * qw[d * 8 + k];
                gB += wv * bs[d];
            }
        }
    }
    float b0r, b1r, b2r, b3r;
    {
        float bb0 = 0, bb1 = 0, bb2 = 0, bb3 = 0;
        const float4* wc = (const float4*)(W_ih + (size_t)row * INW + DM);
#pragma unroll 4
        for (int q = 0; q < LAT / 4; q++) {
            float4 w = wc[q];
            int j = q * 4;
            bb0 += w.x * ctxs[j] + w.y * ctxs[j + 1] + w.z * ctxs[j + 2] + w.w * ctxs[j + 3];
            bb1 += w.x * ctxs[256 + j] + w.y * ctxs[256 + j + 1] + w.z * ctxs[256 + j + 2] + w.w * ctxs[256 + j + 3];
            bb2 += w.x * ctxs[512 + j] + w.y * ctxs[512 + j + 1] + w.z * ctxs[512 + j + 2] + w.w * ctxs[512 + j + 3];
            bb3 += w.x * ctxs[768 + j] + w.y * ctxs[768 + j + 1] + w.z * ctxs[768 + j + 2] + w.w * ctxs[768 + j + 3];
        }
        b0r = gB + bb0;
        b1r = gB + bb1;
        b2r = gB + bb2;
        b3r = gB + bb3;
    }
    uint64_t ac2[8];
#pragma unroll
    for (int k = 0; k < 7; k++) ac2[k] = pk(ac[2 * k], ac[2 * k + 1]);
    ac2[7] = pk(0.0f, 0.0f);
    __syncthreads();

    // ---------------- phase 3: x load (padded stride 16) ----------------
    for (int i = t; i < 4 * SS * XPAD; i += 256) {
        int b = i >> 13;
        int rem = i & 8191;
        int s = rem >> 4, k = rem & 15;
        xs[i] = (k < XWID) ? x[((size_t)(b4 + b) * SS + s) * XWID + k] : 0.0f;
    }

    // ---------------- comm addresses ----------------
    uint32_t rba[8];   // remote ready-barrier addrs (used by t0)
    if (t == 0) {
#pragma unroll
        for (uint32_t d = 0; d < 8; d++) rba[d] = mapa_rank(rdyBar, d);
    }
    uint32_t ga[8];    // remote pbuf gather addrs for my dim (t<128)
    if (t < 128) {
        uint32_t la = su32(&pbuf[t * 4]);
#pragma unroll
        for (uint32_t d = 0; d < 8; d++) ga[d] = mapa_rank(la, d);
    }
    const int cb = t >> 6, cj = t & 63;       // c-update roles
    const int bh = t >> 7, dout = t & 127;    // projection roles
    float c_reg = 0.0f;
    __syncthreads();
    cl_sync();

    const ulonglong2* hp0 = (const ulonglong2*)(hbuf);
    const ulonglong2* hp1 = (const ulonglong2*)(hbuf + 128);
    const ulonglong2* hp2 = (const ulonglong2*)(hbuf + 256);
    const ulonglong2* hp3 = (const ulonglong2*)(hbuf + 384);
    const ulonglong2* xp0 = (const ulonglong2*)(xs + 0 * 8192);
    const ulonglong2* xp1 = (const ulonglong2*)(xs + 1 * 8192);
    const ulonglong2* xp2 = (const ulonglong2*)(xs + 2 * 8192);
    const ulonglong2* xp3 = (const ulonglong2*)(xs + 3 * 8192);

    // =================== main sequential loop ===================
    for (int s = 0; s < SS; s++) {
        // ---- gates: base + W_hh.h + AC.x, 4 batches per thread ----
        uint64_t a0 = pk(b0r, 0.0f);
        uint64_t a1 = pk(b1r, 0.0f);
        uint64_t a2 = pk(b2r, 0.0f);
        uint64_t a3 = pk(b3r, 0.0f);
#pragma unroll
        for (int q = 0; q < 32; q++) {
            ulonglong2 v0 = hp0[q], v1 = hp1[q], v2 = hp2[q], v3 = hp3[q];
            fma2(a0, w2[2 * q], v0.x); fma2(a0, w2[2 * q + 1], v0.y);
            fma2(a1, w2[2 * q], v1.x); fma2(a1, w2[2 * q + 1], v1.y);
            fma2(a2, w2[2 * q], v2.x); fma2(a2, w2[2 * q + 1], v2.y);
            fma2(a3, w2[2 * q], v3.x); fma2(a3, w2[2 * q + 1], v3.y);
        }
        {
            int xo = s * 2;  // ulonglong2 index = s*16 floats / 8
#pragma unroll
            for (int q = 0; q < 4; q++) {
                // each ulonglong2 = 4 floats; 4 per step (16 padded floats)
            }
            const ulonglong2* e0 = xp0 + s * 4;
            const ulonglong2* e1 = xp1 + s * 4;
            const ulonglong2* e2 = xp2 + s * 4;
            const ulonglong2* e3 = xp3 + s * 4;
            (void)xo;
#pragma unroll
            for (int q = 0; q < 4; q++) {
                ulonglong2 u0 = e0[q], u1 = e1[q], u2 = e2[q], u3 = e3[q];
                fma2(a0, ac2[2 * q], u0.x); fma2(a0, ac2[2 * q + 1], u0.y);
                fma2(a1, ac2[2 * q], u1.x); fma2(a1, ac2[2 * q + 1], u1.y);
                fma2(a2, ac2[2 * q], u2.x); fma2(a2, ac2[2 * q + 1], u2.y);
                fma2(a3, ac2[2 * q], u3.x); fma2(a3, ac2[2 * q + 1], u3.y);
            }
        }
        float lo, hi, g0, g1, g2, g3;
        upk(a0, lo, hi); g0 = lo + hi;
        upk(a1, lo, hi); g1 = lo + hi;
        upk(a2, lo, hi); g2 = lo + hi;
        upk(a3, lo, hi); g3 = lo + hi;
        if (gt == 2) { g0 = ftanh(g0); g1 = ftanh(g1); g2 = ftanh(g2); g3 = ftanh(g3); }
        else         { g0 = fsig(g0);  g1 = fsig(g1);  g2 = fsig(g2);  g3 = fsig(g3);  }
        gbuf[gt * 256 + 0 * 64 + cl] = g0;
        gbuf[gt * 256 + 1 * 64 + cl] = g1;
        gbuf[gt * 256 + 2 * 64 + cl] = g2;
        gbuf[gt * 256 + 3 * 64 + cl] = g3;
        __syncthreads();

        // ---- c update: one c-state per thread; a = o * tanh(c) ----
        {
            float gi = gbuf[0 * 256 + cb * 64 + cj];
            float gf = gbuf[1 * 256 + cb * 64 + cj];
            float gg = gbuf[2 * 256 + cb * 64 + cj];
            float gO = gbuf[3 * 256 + cb * 64 + cj];
            c_reg = gf * c_reg + gi * gg;
            abuf[cb * 64 + cj] = gO * ftanh(c_reg);
        }
        __syncthreads();

        // ---- projection partials: (dout, batches 2bh, 2bh+1) ----
        float pe = 0.0f, po = 0.0f;
        {
            const float4* aqe = (const float4*)(abuf + (2 * bh) * 64);
            const float4* aqo = (const float4*)(abuf + (2 * bh + 1) * 64);
#pragma unroll
            for (int q = 0; q < 16; q++) {
                int j = q * 4;
                float4 va = aqe[q];
                float4 vb = aqo[q];
                float wv0 = whr[(j + 0) * 128 + dout];
                float wv1 = whr[(j + 1) * 128 + dout];
                float wv2 = whr[(j + 2) * 128 + dout];
                float wv3 = whr[(j + 3) * 128 + dout];
                pe += va.x * wv0 + va.y * wv1 + va.z * wv2 + va.w * wv3;
                po += vb.x * wv0 + vb.y * wv1 + vb.z * wv2 + vb.w * wv3;
            }
        }
        {
            float2* dst = (float2*)(pbuf + (s & 1) * 512 + dout * 4 + 2 * bh);
            *dst = make_float2(pe, po);
        }
        __syncthreads();

        // ---- notify all ranks: my partials for step s are ready ----
        if (t == 0) {
#pragma unroll
            for (int d = 0; d < 8; d++) mbar_arrive_cluster(rba[d]);
        }
        mbar_wait(rdyBar, (uint32_t)s & 1u);

        // ---- pull-gather: h[d] = sum over ranks of partial[d] ----
        if (t < 128) {
            uint32_t off = ((uint32_t)s & 1u) * 2048u;
            float4 acc = ldsc_v4(ga[0] + off);
#pragma unroll
            for (int r = 1; r < 8; r++) {
                float4 v = ldsc_v4(ga[r] + off);
                acc.x += v.x; acc.y += v.y; acc.z += v.z; acc.w += v.w;
            }
            hbuf[0 * 128 + t] = acc.x;
            hbuf[1 * 128 + t] = acc.y;
            hbuf[2 * 128 + t] = acc.z;
            hbuf[3 * 128 + t] = acc.w;
            if (rank < 4) {
                float hv = (rank == 0) ? acc.x : (rank == 1) ? acc.y
                         : (rank == 2) ? acc.z : acc.w;
                g_hs[((size_t)(b4 + (int)rank) * SS + s) * PROJ + t] = hv;
            }
        }
        __syncthreads();
    }
    cl_sync();
}

// =====================================================================
// Head kernel: LayerNorm + output heads. One warp per (b,s) row.
// =====================================================================
__global__ void __launch_bounds__(256)
head_kernel(const float* __restrict__ lng, const float* __restrict__ lnb,
            const float* __restrict__ ocW, const float* __restrict__ ocb,
            const float* __restrict__ oxW, const float* __restrict__ oxb,
            const float* __restrict__ scl, float* __restrict__ out)
{
    const size_t OUT_OFF = (size_t)BB * SS * NCW;
    int lane = threadIdx.x & 31;
    int row = blockIdx.x * 8 + (threadIdx.x >> 5);

    const float4 h4 = ((const float4*)g_hs)[(size_t)row * 32 + lane];
    float s = h4.x + h4.y + h4.z + h4.w;
    s = warp_sum(s);
    float mu = s * (1.0f / 128.0f);
    float dx = h4.x - mu, dy = h4.y - mu, dz = h4.z - mu, dw = h4.w - mu;
    float sq = dx * dx + dy * dy + dz * dz + dw * dw;
    sq = warp_sum(sq);
    float rs = rsqrtf(sq * (1.0f / 128.0f) + 1e-5f);

    float4 lg = ((const float4*)lng)[lane];
    float4 lb = ((const float4*)lnb)[lane];
    float y0 = dx * rs * lg.x + lb.x;
    float y1 = dy * rs * lg.y + lb.y;
    float y2 = dz * rs * lg.z + lb.z;
    float y3 = dw * rs * lg.w + lb.w;

    float l0, l1, l2, l3, l4, l5;
#define DOLOGIT(m, dst)                                                         \
    {                                                                           \
        const float* wrow = ocW + (m) * PROJ + lane * 4;                        \
        float p = y0 * wrow[0] + y1 * wrow[1] + y2 * wrow[2] + y3 * wrow[3];    \
        p = warp_sum(p);                                                        \
        dst = p + ocb[m];                                                       \
        if (lane == (m)) out[(size_t)row * NCW + (m)] = dst;                    \
    }
    DOLOGIT(0, l0) DOLOGIT(1, l1) DOLOGIT(2, l2)
    DOLOGIT(3, l3) DOLOGIT(4, l4) DOLOGIT(5, l5)
#undef DOLOGIT

    float scale = scl[0];
#define DOCOORD(m)                                                              \
    {                                                                           \
        const float* wrow = oxW + (m) * (PROJ + NCW) + lane * 4;                \
        float p = y0 * wrow[0] + y1 * wrow[1] + y2 * wrow[2] + y3 * wrow[3];    \
        p = warp_sum(p);                                                        \
        const float* wt = oxW + (m) * (PROJ + NCW) + PROJ;                      \
        float tot = p + l0 * wt[0] + l1 * wt[1] + l2 * wt[2] + l3 * wt[3]       \
                      + l4 * wt[4] + l5 * wt[5] + oxb[m];                       \
        float co = tanhf(tot * scale);                                          \
        if (lane == (m)) out[OUT_OFF + (size_t)row * NCW + (m)] = co;           \
    }
    DOCOORD(0) DOCOORD(1) DOCOORD(2) DOCOORD(3) DOCOORD(4) DOCOORD(5)
#undef DOCOORD
}

// =====================================================================
extern "C" void kernel_launch(void* const* d_in, const int* in_sizes, int n_in,
                              void* d_out, int out_size)
{
    (void)in_sizes; (void)n_in; (void)out_size;
    const float* x           = (const float*)d_in[0];
    const float* context     = (const float*)d_in[1];
    const float* cmd_W       = (const float*)d_in[2];
    const float* cmd_b       = (const float*)d_in[3];
    const float* coord_W     = (const float*)d_in[4];
    const float* coord_b     = (const float*)d_in[5];
    const float* W_ih        = (const float*)d_in[6];
    const float* W_hh        = (const float*)d_in[7];
    const float* b_ih        = (const float*)d_in[8];
    const float* b_hh        = (const float*)d_in[9];
    const float* W_hr        = (const float*)d_in[10];
    const float* ln_g        = (const float*)d_in[11];
    const float* ln_b        = (const float*)d_in[12];
    const float* outc_W      = (const float*)d_in[13];
    const float* outc_b      = (const float*)d_in[14];
    const float* outx_W      = (const float*)d_in[15];
    const float* outx_b      = (const float*)d_in[16];
    const float* coord_scale = (const float*)d_in[17];
    float* out = (float*)d_out;

    cudaFuncSetAttribute(scan_kernel,
                         cudaFuncAttributeMaxDynamicSharedMemorySize,
                         SM_TOT_BYTES);

    scan_kernel<<<128, 256, SM_TOT_BYTES>>>(x, context, cmd_W, cmd_b,
                                            coord_W, coord_b, W_ih, W_hh,
                                            b_ih, b_hh, W_hr);
    head_kernel<<<BB * SS / 8, 256>>>(ln_g, ln_b, outc_W, outc_b,
                                      outx_W, outx_b, coord_scale, out);
}

// round 7
// speedup vs baseline: 1.6514x; 1.6514x over previous
#include <cuda_runtime.h>
#include <cstdint>
#include <cstddef>

#define XWID  14
#define XPAD  16
#define PROJ  128
#define DM    512
#define LAT   256
#define BB    64
#define SS    512
#define NCW   6
#define INW   768

// ------------- smem layout (float offsets) -------------
#define SM_H     0        // [b<4][128]                    512
#define SM_RECV  512      // [src8][jh2][od16][k2] float2  1024
#define SM_A     1536     // [cd<64] float4                256
#define SM_CTX   1792     // [b<4][256]                    1024
#define SM_BARS  2816     // 2 x u64 barriers              4
#define SM_PAD   2820     // pad                           12
#define SM_X     2832     // [b<4][512][16]                32768
#define SM_TOT_FLOATS 35600
#define SM_TOT_BYTES  (SM_TOT_FLOATS * 4)

// history for head kernel
__device__ __align__(16) float g_hs[(size_t)BB * SS * PROJ];

// ---------------- helpers ----------------
static __device__ __forceinline__ uint32_t su32(const void* p) {
    return (uint32_t)__cvta_generic_to_shared(p);
}
static __device__ __forceinline__ uint32_t mapa_rank(uint32_t a, uint32_t r) {
    uint32_t o;
    asm("mapa.shared::cluster.u32 %0, %1, %2;" : "=r"(o) : "r"(a), "r"(r));
    return o;
}
static __device__ __forceinline__ uint32_t ctarank() {
    uint32_t r;
    asm("mov.u32 %0, %%cluster_ctarank;" : "=r"(r));
    return r;
}
static __device__ __forceinline__ void cl_sync() {
    asm volatile("barrier.cluster.arrive.aligned;" ::: "memory");
    asm volatile("barrier.cluster.wait.aligned;" ::: "memory");
}
static __device__ __forceinline__ void mbar_init(uint32_t bar, uint32_t cnt) {
    asm volatile("mbarrier.init.shared.b64 [%0], %1;" :: "r"(bar), "r"(cnt) : "memory");
}
static __device__ __forceinline__ void mbar_arm(uint32_t bar, uint32_t tx) {
    asm volatile("mbarrier.arrive.expect_tx.shared.b64 _, [%0], %1;"
                 :: "r"(bar), "r"(tx) : "memory");
}
static __device__ __forceinline__ void mbar_wait(uint32_t bar, uint32_t ph) {
    uint32_t done;
    asm volatile(
        "{\n\t.reg .pred p;\n\t"
        "mbarrier.try_wait.parity.acquire.cluster.shared::cta.b64 p, [%1], %2;\n\t"
        "selp.b32 %0, 1, 0, p;\n\t}"
        : "=r"(done) : "r"(bar), "r"(ph) : "memory");
    if (!done) {
        asm volatile(
            "{\n\t.reg .pred P1;\n"
            "WL%=:\n\t"
            "mbarrier.try_wait.parity.acquire.cluster.shared::cta.b64 P1, [%0], %1, 0x989680;\n\t"
            "@P1 bra.uni WD%=;\n\t"
            "bra.uni WL%=;\n"
            "WD%=:\n\t}"
            :: "r"(bar), "r"(ph) : "memory");
    }
}
static __device__ __forceinline__ void sta32(uint32_t addr, float v, uint32_t bar) {
    asm volatile(
        "st.async.shared::cluster.mbarrier::complete_tx::bytes.b32 [%0], %1, [%2];"
        :: "r"(addr), "r"(__float_as_uint(v)), "r"(bar) : "memory");
}
static __device__ __forceinline__ void sta64(uint32_t addr, uint64_t v, uint32_t bar) {
    asm volatile(
        "st.async.shared::cluster.mbarrier::complete_tx::bytes.b64 [%0], %1, [%2];"
        :: "r"(addr), "l"(v), "r"(bar) : "memory");
}
static __device__ __forceinline__ uint64_t pk(float lo, float hi) {
    uint64_t r;
    asm("mov.b64 %0, {%1, %2};" : "=l"(r) : "f"(lo), "f"(hi));
    return r;
}
static __device__ __forceinline__ void upk(uint64_t v, float& lo, float& hi) {
    asm("mov.b64 {%0, %1}, %2;" : "=f"(lo), "=f"(hi) : "l"(v));
}
static __device__ __forceinline__ void fma2(uint64_t& a, uint64_t b, uint64_t c) {
    asm("fma.rn.f32x2 %0, %1, %2, %0;" : "+l"(a) : "l"(b), "l"(c));
}
static __device__ __forceinline__ float ex2f(float x) {
    float r;
    asm("ex2.approx.f32 %0, %1;" : "=f"(r) : "f"(x));
    return r;
}
static __device__ __forceinline__ float rcpf(float x) {
    float r;
    asm("rcp.approx.f32 %0, %1;" : "=f"(r) : "f"(x));
    return r;
}
static __device__ __forceinline__ float ftanh(float x) {
    return fmaf(2.0f, rcpf(1.0f + ex2f(-2.8853900817779268f * x)), -1.0f);
}
static __device__ __forceinline__ float warp_sum(float v) {
#pragma unroll
    for (int m = 16; m > 0; m >>= 1) v += __shfl_xor_sync(0xffffffffu, v, m);
    return v;
}

// tiny kernel to align ncu's -s 5 -c 1 onto scan_kernel (launch period 4)
__global__ void noop_kernel() {}

// =====================================================================
// Scan kernel: 128 CTAs, cluster 8, 256 threads.
// Cluster handles batches [4*cl, 4*cl+4). Rank owns c-dims [64r,64r+64).
// Thread map (gates): warp w, lane l -> gate type gty=l>>3, c-dim
// cd = 8w + (l&7); thread computes that gate for 4 batches (W_hh row in
// 128 regs). c-update via shfl_down within the warp. Projection: thread
// (jh = t>>7, dout = t&127) covers 32 j's x 4 batches with W_hr weights
// in registers; packed f32x2 partials sent via one st.async.b64 per pair
// to the owner rank. Owners are warps 6-7 (hi-wid arbiter priority):
// reduce 16 sources, broadcast h via st.async, store history.
// =====================================================================
__global__ void __cluster_dims__(8, 1, 1) __launch_bounds__(256, 1)
scan_kernel(const float* __restrict__ x, const float* __restrict__ ctx,
            const float* __restrict__ cmdW, const float* __restrict__ cmdb,
            const float* __restrict__ coordW, const float* __restrict__ coordb,
            const float* __restrict__ W_ih, const float* __restrict__ W_hh,
            const float* __restrict__ bih, const float* __restrict__ bhh,
            const float* __restrict__ W_hr)
{
    extern __shared__ float sm[];
    float*  hbuf  = sm + SM_H;
    float*  recv  = sm + SM_RECV;
    float4* abuf4 = (float4*)(sm + SM_A);
    float*  ctxs  = sm + SM_CTX;
    float*  xs    = sm + SM_X;

    const int t = threadIdx.x;
    const int lane = t & 31, wrp = t >> 5;
    const uint32_t rank = ctarank();
    const int b4 = (blockIdx.x >> 3) * 4;
    const int gty = lane >> 3;
    const int cd  = 8 * wrp + (lane & 7);
    const int row = gty * 512 + (int)rank * 64 + cd;

    // --- W_hh row into packed registers (64 x u64 = 128 floats) ---
    uint64_t w2[64];
    {
        const ulonglong2* p = (const ulonglong2*)(W_hh + (size_t)row * PROJ);
#pragma unroll
        for (int q = 0; q < 32; q++) {
            ulonglong2 v = p[q];
            w2[2 * q] = v.x;
            w2[2 * q + 1] = v.y;
        }
    }
    // --- W_hr slice into registers: thread (jh, dout) ---
    const int jh = t >> 7, dout = t & 127;
    float wp[32];
#pragma unroll
    for (int jj = 0; jj < 32; jj++)
        wp[jj] = W_hr[(size_t)dout * DM + (int)rank * 64 + jh * 32 + jj];

    // ---------------- prologue phase 1: small smem loads ----------------
    float* cw = xs;           // 3072
    float* qw = xs + 3072;    // 4096
    float* bs = xs + 7168;    // 512
    for (int i = t; i < DM * 6; i += 256) cw[i] = cmdW[i];
    for (int i = t; i < DM * 8; i += 256) qw[i] = coordW[i];
    for (int i = t; i < DM; i += 256) bs[i] = cmdb[i] + coordb[i];
    for (int i = t; i < 4 * LAT; i += 256) {
        int b = i >> 8, j = i & 255;
        ctxs[i] = ctx[(size_t)(b4 + b) * LAT + j];
    }
    for (int i = t; i < 512; i += 256) hbuf[i] = 0.0f;
    const uint32_t barF = su32(sm + SM_BARS);
    const uint32_t barH = su32(sm + SM_BARS) + 8;
    if (t == 0) {
        mbar_init(barF, 1);
        mbar_init(barH, 1);
        mbar_arm(barF, 4096);
        mbar_arm(barH, 2048);
    }
    __syncthreads();

    // ---------------- phase 2: fold input weights + per-batch base -------
    float ac[XWID];
#pragma unroll
    for (int k = 0; k < XWID; k++) ac[k] = 0.0f;
    float gB = bih[row] + bhh[row];
    {
        const float4* wr = (const float4*)(W_ih + (size_t)row * INW);
        for (int d4 = 0; d4 < DM / 4; d4++) {
            float4 w4 = wr[d4];
            float wa[4] = {w4.x, w4.y, w4.z, w4.w};
#pragma unroll
            for (int u = 0; u < 4; u++) {
                int d = d4 * 4 + u;
                float wv = wa[u];
#pragma unroll
                for (int k = 0; k < 6; k++) ac[k] += wv * cw[d * 6 + k];
#pragma unroll
                for (int k = 0; k < 8; k++) ac[6 + k] += wv * qw[d * 8 + k];
                gB += wv * bs[d];
            }
        }
    }
    float b0r, b1r, b2r, b3r;
    {
        float bb0 = 0, bb1 = 0, bb2 = 0, bb3 = 0;
        const float4* wc = (const float4*)(W_ih + (size_t)row * INW + DM);
#pragma unroll 4
        for (int q = 0; q < LAT / 4; q++) {
            float4 w = wc[q];
            int j = q * 4;
            bb0 += w.x * ctxs[j] + w.y * ctxs[j + 1] + w.z * ctxs[j + 2] + w.w * ctxs[j + 3];
            bb1 += w.x * ctxs[256 + j] + w.y * ctxs[256 + j + 1] + w.z * ctxs[256 + j + 2] + w.w * ctxs[256 + j + 3];
            bb2 += w.x * ctxs[512 + j] + w.y * ctxs[512 + j + 1] + w.z * ctxs[512 + j + 2] + w.w * ctxs[512 + j + 3];
            bb3 += w.x * ctxs[768 + j] + w.y * ctxs[768 + j + 1] + w.z * ctxs[768 + j + 2] + w.w * ctxs[768 + j + 3];
        }
        b0r = gB + bb0;
        b1r = gB + bb1;
        b2r = gB + bb2;
        b3r = gB + bb3;
    }
    uint64_t ac2[8];
#pragma unroll
    for (int k = 0; k < 7; k++) ac2[k] = pk(ac[2 * k], ac[2 * k + 1]);
    ac2[7] = pk(0.0f, 0.0f);
    __syncthreads();

    // ---------------- phase 3: x load (padded stride 16) ----------------
    for (int i = t; i < 4 * SS * XPAD; i += 256) {
        int b = i >> 13;
        int rem = i & 8191;
        int s = rem >> 4, k = rem & 15;
        xs[i] = (k < XWID) ? x[((size_t)(b4 + b) * SS + s) * XWID + k] : 0.0f;
    }

    // ---------------- comm addresses ----------------
    // sender: partial pairs to owner rank ow = dout>>4.
    // recv layout (float2 units): [src8][jh2][od16][k2]
    const uint32_t ow = (uint32_t)(dout >> 4);
    const uint32_t psend = mapa_rank(
        su32(recv) + ((((rank * 2u + (uint32_t)jh) * 16u + (uint32_t)(dout & 15)) * 2u) * 8u), ow);
    const uint32_t pfb = mapa_rank(barF, ow);

    // owner roles: t in [192,256)
    uint32_t hdst[8], hbb[8];
    int ob = 0, od = 0;
    if (t >= 192) {
        int u = t - 192;
        ob = u >> 4; od = u & 15;
        uint32_t la = su32(&hbuf[ob * 128 + (int)rank * 16 + od]);
#pragma unroll
        for (uint32_t d = 0; d < 8; d++) {
            hdst[d] = mapa_rank(la, d);
            hbb[d]  = mapa_rank(barH, d);
        }
    }
    // activation constants (uniform formula, no divergence)
    const float s1 = (gty == 2) ? -2.8853900817779268f : -1.4426950408889634f;
    const float mm = (gty == 2) ? 2.0f : 1.0f;
    const float cc = (gty == 2) ? -1.0f : 0.0f;
    float c0 = 0.0f, c1 = 0.0f, c2 = 0.0f, c3 = 0.0f;
    __syncthreads();
    cl_sync();

    const ulonglong2* hp0 = (const ulonglong2*)(hbuf);
    const ulonglong2* hp1 = (const ulonglong2*)(hbuf + 128);
    const ulonglong2* hp2 = (const ulonglong2*)(hbuf + 256);
    const ulonglong2* hp3 = (const ulonglong2*)(hbuf + 384);

    // =================== main sequential loop ===================
    for (int s = 0; s < SS; s++) {
        // ---- gates: base + W_hh.h + AC.x, 4 batches per thread ----
        uint64_t a0 = pk(b0r, 0.0f);
        uint64_t a1 = pk(b1r, 0.0f);
        uint64_t a2 = pk(b2r, 0.0f);
        uint64_t a3 = pk(b3r, 0.0f);
#pragma unroll
        for (int q = 0; q < 32; q++) {
            ulonglong2 v0 = hp0[q], v1 = hp1[q], v2 = hp2[q], v3 = hp3[q];
            fma2(a0, w2[2 * q], v0.x); fma2(a0, w2[2 * q + 1], v0.y);
            fma2(a1, w2[2 * q], v1.x); fma2(a1, w2[2 * q + 1], v1.y);
            fma2(a2, w2[2 * q], v2.x); fma2(a2, w2[2 * q + 1], v2.y);
            fma2(a3, w2[2 * q], v3.x); fma2(a3, w2[2 * q + 1], v3.y);
        }
        {
            const ulonglong2* e0 = (const ulonglong2*)(xs + 0 * 8192 + s * XPAD);
            const ulonglong2* e1 = (const ulonglong2*)(xs + 1 * 8192 + s * XPAD);
            const ulonglong2* e2 = (const ulonglong2*)(xs + 2 * 8192 + s * XPAD);
            const ulonglong2* e3 = (const ulonglong2*)(xs + 3 * 8192 + s * XPAD);
#pragma unroll
            for (int q = 0; q < 4; q++) {
                ulonglong2 u0 = e0[q], u1 = e1[q], u2 = e2[q], u3 = e3[q];
                fma2(a0, ac2[2 * q], u0.x); fma2(a0, ac2[2 * q + 1], u0.y);
                fma2(a1, ac2[2 * q], u1.x); fma2(a1, ac2[2 * q + 1], u1.y);
                fma2(a2, ac2[2 * q], u2.x); fma2(a2, ac2[2 * q + 1], u2.y);
                fma2(a3, ac2[2 * q], u3.x); fma2(a3, ac2[2 * q + 1], u3.y);
            }
        }
        float lo, hi, v0, v1, v2, v3;
        upk(a0, lo, hi); v0 = lo + hi;
        upk(a1, lo, hi); v1 = lo + hi;
        upk(a2, lo, hi); v2 = lo + hi;
        upk(a3, lo, hi); v3 = lo + hi;
        // uniform activation: sigmoid (gty!=2) or tanh (gty==2)
        v0 = fmaf(mm, rcpf(1.0f + ex2f(s1 * v0)), cc);
        v1 = fmaf(mm, rcpf(1.0f + ex2f(s1 * v1)), cc);
        v2 = fmaf(mm, rcpf(1.0f + ex2f(s1 * v2)), cc);
        v3 = fmaf(mm, rcpf(1.0f + ex2f(s1 * v3)), cc);

        // ---- c-update via shfl: i-lanes (0-7) gather f,g,o ----
        float f0 = __shfl_down_sync(0xffffffffu, v0, 8);
        float f1 = __shfl_down_sync(0xffffffffu, v1, 8);
        float f2 = __shfl_down_sync(0xffffffffu, v2, 8);
        float f3 = __shfl_down_sync(0xffffffffu, v3, 8);
        float g0 = __shfl_down_sync(0xffffffffu, v0, 16);
        float g1 = __shfl_down_sync(0xffffffffu, v1, 16);
        float g2 = __shfl_down_sync(0xffffffffu, v2, 16);
        float g3 = __shfl_down_sync(0xffffffffu, v3, 16);
        float o0 = __shfl_down_sync(0xffffffffu, v0, 24);
        float o1 = __shfl_down_sync(0xffffffffu, v1, 24);
        float o2 = __shfl_down_sync(0xffffffffu, v2, 24);
        float o3 = __shfl_down_sync(0xffffffffu, v3, 24);
        if (lane < 8) {
            c0 = f0 * c0 + v0 * g0;
            c1 = f1 * c1 + v1 * g1;
            c2 = f2 * c2 + v2 * g2;
            c3 = f3 * c3 + v3 * g3;
            float aa0 = o0 * ftanh(c0);
            float aa1 = o1 * ftanh(c1);
            float aa2 = o2 * ftanh(c2);
            float aa3 = o3 * ftanh(c3);
            abuf4[cd] = make_float4(aa0, aa2, aa1, aa3);  // pairs (b0,b2),(b1,b3)
        }
        __syncthreads();

        // ---- projection: 32 j's x 4 batches, weights in regs ----
        uint64_t pA = pk(0.0f, 0.0f);   // (b0, b2)
        uint64_t pB = pk(0.0f, 0.0f);   // (b1, b3)
        {
            const ulonglong2* ap = (const ulonglong2*)(abuf4 + jh * 32);
#pragma unroll
            for (int jj = 0; jj < 32; jj++) {
                ulonglong2 av = ap[jj];
                uint64_t wd = pk(wp[jj], wp[jj]);
                fma2(pA, wd, av.x);
                fma2(pB, wd, av.y);
            }
        }
        sta64(psend, pA, pfb);
        sta64(psend + 8, pB, pfb);

        // ---- owners (warps 6-7): reduce 16 sources + broadcast ----
        if (t >= 192) {
            mbar_wait(barF, (uint32_t)s & 1u);
            if (t == 192) mbar_arm(barF, 4096);
            const int k = ob & 1, sel = ob >> 1;
            float hv = 0.0f;
#pragma unroll
            for (int src = 0; src < 16; src++)
                hv += recv[((src * 16 + od) * 2 + k) * 2 + sel];
            g_hs[((size_t)(b4 + ob) * SS + s) * PROJ + (int)rank * 16 + od] = hv;
#pragma unroll
            for (int d = 0; d < 8; d++) sta32(hdst[d], hv, hbb[d]);
        }

        // ---- everyone: wait for next h ----
        mbar_wait(barH, (uint32_t)s & 1u);
        if (t == 0) mbar_arm(barH, 2048);
    }
    cl_sync();
}

// =====================================================================
// Head kernel: LayerNorm + output heads. One warp per (b,s) row.
// =====================================================================
__global__ void __launch_bounds__(256)
head_kernel(const float* __restrict__ lng, const float* __restrict__ lnb,
            const float* __restrict__ ocW, const float* __restrict__ ocb,
            const float* __restrict__ oxW, const float* __restrict__ oxb,
            const float* __restrict__ scl, float* __restrict__ out)
{
    const size_t OUT_OFF = (size_t)BB * SS * NCW;
    int lane = threadIdx.x & 31;
    int row = blockIdx.x * 8 + (threadIdx.x >> 5);

    const float4 h4 = ((const float4*)g_hs)[(size_t)row * 32 + lane];
    float s = h4.x + h4.y + h4.z + h4.w;
    s = warp_sum(s);
    float mu = s * (1.0f / 128.0f);
    float dx = h4.x - mu, dy = h4.y - mu, dz = h4.z - mu, dw = h4.w - mu;
    float sq = dx * dx + dy * dy + dz * dz + dw * dw;
    sq = warp_sum(sq);
    float rs = rsqrtf(sq * (1.0f / 128.0f) + 1e-5f);

    float4 lg = ((const float4*)lng)[lane];
    float4 lb = ((const float4*)lnb)[lane];
    float y0 = dx * rs * lg.x + lb.x;
    float y1 = dy * rs * lg.y + lb.y;
    float y2 = dz * rs * lg.z + lb.z;
    float y3 = dw * rs * lg.w + lb.w;

    float l0, l1, l2, l3, l4, l5;
#define DOLOGIT(m, dst)                                                         \
    {                                                                           \
        const float* wrow = ocW + (m) * PROJ + lane * 4;                        \
        float p = y0 * wrow[0] + y1 * wrow[1] + y2 * wrow[2] + y3 * wrow[3];    \
        p = warp_sum(p);                                                        \
        dst = p + ocb[m];                                                       \
        if (lane == (m)) out[(size_t)row * NCW + (m)] = dst;                    \
    }
    DOLOGIT(0, l0) DOLOGIT(1, l1) DOLOGIT(2, l2)
    DOLOGIT(3, l3) DOLOGIT(4, l4) DOLOGIT(5, l5)
#undef DOLOGIT

    float scale = scl[0];
#define DOCOORD(m)                                                              \
    {                                                                           \
        const float* wrow = oxW + (m) * (PROJ + NCW) + lane * 4;                \
        float p = y0 * wrow[0] + y1 * wrow[1] + y2 * wrow[2] + y3 * wrow[3];    \
        p = warp_sum(p);                                                        \
        const float* wt = oxW + (m) * (PROJ + NCW) + PROJ;                      \
        float tot = p + l0 * wt[0] + l1 * wt[1] + l2 * wt[2] + l3 * wt[3]       \
                      + l4 * wt[4] + l5 * wt[5] + oxb[m];                       \
        float co = tanhf(tot * scale);                                          \
        if (lane == (m)) out[OUT_OFF + (size_t)row * NCW + (m)] = co;           \
    }
    DOCOORD(0) DOCOORD(1) DOCOORD(2) DOCOORD(3) DOCOORD(4) DOCOORD(5)
#undef DOCOORD
}

// =====================================================================
extern "C" void kernel_launch(void* const* d_in, const int* in_sizes, int n_in,
                              void* d_out, int out_size)
{
    (void)in_sizes; (void)n_in; (void)out_size;
    const float* x           = (const float*)d_in[0];
    const float* context     = (const float*)d_in[1];
    const float* cmd_W       = (const float*)d_in[2];
    const float* cmd_b       = (const float*)d_in[3];
    const float* coord_W     = (const float*)d_in[4];
    const float* coord_b     = (const float*)d_in[5];
    const float* W_ih        = (const float*)d_in[6];
    const float* W_hh        = (const float*)d_in[7];
    const float* b_ih        = (const float*)d_in[8];
    const float* b_hh        = (const float*)d_in[9];
    const float* W_hr        = (const float*)d_in[10];
    const float* ln_g        = (const float*)d_in[11];
    const float* ln_b        = (const float*)d_in[12];
    const float* outc_W      = (const float*)d_in[13];
    const float* outc_b      = (const float*)d_in[14];
    const float* outx_W      = (const float*)d_in[15];
    const float* outx_b      = (const float*)d_in[16];
    const float* coord_scale = (const float*)d_in[17];
    float* out = (float*)d_out;

    cudaFuncSetAttribute(scan_kernel,
                         cudaFuncAttributeMaxDynamicSharedMemorySize,
                         SM_TOT_BYTES);

    // launch period of 4 with scan at position 2 (mod 4): ncu -s 5 -c 1
    // lands on scan_kernel (launch #6).
    noop_kernel<<<1, 32>>>();
    scan_kernel<<<128, 256, SM_TOT_BYTES>>>(x, context, cmd_W, cmd_b,
                                            coord_W, coord_b, W_ih, W_hh,
                                            b_ih, b_hh, W_hr);
    head_kernel<<<BB * SS / 8, 256>>>(ln_g, ln_b, outc_W, outc_b,
                                      outx_W, outx_b, coord_scale, out);
    noop_kernel<<<1, 32>>>();
}